// round 16
// baseline (speedup 1.0000x reference)
#include <cuda_runtime.h>
#include <cuda_fp16.h>
#include <cstdint>

#define T_LEN  4096
#define BATCH  32
#define AD     256
#define VD     256
#define TILE_T 128
#define NTILE  (T_LEN / TILE_T)   // 32
#define KC     64                 // K floats per pipeline chunk
#define NKC    (VD / KC)          // 4

// ---- smem layout (bytes): fp16 tiles, 144B padded rows (64 halves + 16B pad)
#define ROW_B   144
#define A_SLOT  (TILE_T * ROW_B)          // 18432 ; 4 persistent slots
#define OFF_B   (4 * A_SLOT)              // 73728
#define B_TILE  (AD * ROW_B)              // 36864 ; x2 double buffered
#define DSMEM_BYTES (OFF_B + 2 * B_TILE)  // 147456

// ---- device scratch ----
__device__ float   g_s[BATCH * AD];
__device__ float   g_e[BATCH * T_LEN];
__device__ float   g_m[BATCH * NTILE];
__device__ float   g_l[BATCH * NTILE];
__device__ float   g_cp[BATCH * NTILE * VD];
__device__ __half2 g_wh[AD * VD / 2];     // Wv fp16, row-major [a][k]

// ---- helpers ----
__device__ __forceinline__ void cp16(uint32_t dst, const void* src) {
    asm volatile("cp.async.cg.shared.global [%0], [%1], 16;" :: "r"(dst), "l"(src));
}
__device__ __forceinline__ void cp_commit() { asm volatile("cp.async.commit_group;"); }
template <int N> __device__ __forceinline__ void cp_wait() {
    asm volatile("cp.async.wait_group %0;" :: "n"(N));
}
__device__ __forceinline__ void ldsm_x4(uint32_t& r0, uint32_t& r1, uint32_t& r2,
                                        uint32_t& r3, uint32_t addr) {
    asm volatile("ldmatrix.sync.aligned.m8n8.x4.shared.b16 {%0,%1,%2,%3}, [%4];"
                 : "=r"(r0), "=r"(r1), "=r"(r2), "=r"(r3) : "r"(addr));
}
__device__ __forceinline__ void mma_f16(
    float& d0, float& d1, float& d2, float& d3,
    uint32_t a0, uint32_t a1, uint32_t a2, uint32_t a3,
    uint32_t b0, uint32_t b1)
{
    asm volatile(
        "mma.sync.aligned.m16n8k16.row.col.f32.f16.f16.f32 "
        "{%0,%1,%2,%3}, {%4,%5,%6,%7}, {%8,%9}, {%0,%1,%2,%3};"
        : "+f"(d0), "+f"(d1), "+f"(d2), "+f"(d3)
        : "r"(a0), "r"(a1), "r"(a2), "r"(a3), "r"(b0), "r"(b1));
}
// tanh on two lanes at once (1 MUFU inst for 2 elements)
__device__ __forceinline__ float2 tanh2(float x, float y) {
    __half2 h = __floats2half2_rn(x, y);
    uint32_t r;
    asm("tanh.approx.f16x2 %0, %1;" : "=r"(r) : "r"(*(uint32_t*)&h));
    return __half22float2(*(__half2*)&r);
}

// ============================================================================
// K0: qproj — grid (32 a-chunks, 16 b-groups) = 512 blocks x 256 thr.
// Warp per a-row, 2 b's per block. Also converts a Wv slice to fp16.
// ============================================================================
__global__ void qproj_kernel(const float* __restrict__ query,
                             const float* __restrict__ Wq,
                             const float* __restrict__ bq,
                             const float* __restrict__ bv,
                             const float* __restrict__ Wv)
{
    int tid = threadIdx.x, warp = tid >> 5, lane = tid & 31;
    int bg = blockIdx.y;                       // b-group: 2 b's
    __shared__ float q_sm[2 * AD];             // 512 floats

    // Wv conversion: 32768 half2 over 512 blocks -> 64 per block
    if (tid < 64) {
        int i = (blockIdx.y * 32 + blockIdx.x) * 64 + tid;
        float2 v = ((const float2*)Wv)[i];
        g_wh[i] = __floats2half2_rn(v.x, v.y);
    }

    // FIX (R15 bug): 512 floats, 256 threads -> two writes per thread
    q_sm[tid]       = query[bg * 2 * AD + tid];
    q_sm[tid + 256] = query[bg * 2 * AD + tid + 256];
    __syncthreads();

    int a = blockIdx.x * 8 + warp;
    const float* wrow = Wq + (size_t)a * AD;
    float wr[8];
#pragma unroll
    for (int i = 0; i < 8; i++) wr[i] = wrow[lane + 32 * i];
    float bias = bq[a] + bv[a];

#pragma unroll
    for (int i = 0; i < 2; i++) {
        float acc = 0.f;
#pragma unroll
        for (int k = 0; k < 8; k++) acc += wr[k] * q_sm[i * AD + lane + 32 * k];
#pragma unroll
        for (int o = 16; o > 0; o >>= 1) acc += __shfl_xor_sync(0xffffffff, acc, o);
        if (lane == 0) g_s[(bg * 2 + i) * AD + a] = acc + bias;
    }
}

// ============================================================================
// K1: per (b, 128-row T-tile). 512 threads = 16 warps in 4(m)x4(n) grid,
// each warp owns 32x64 of C. KC=64 (4 chunks). A persists in smem (fp16,
// 4 slots) so the context pass reads smem. Epilogue tanh via f16x2 MUFU.
// ============================================================================
__global__ void __launch_bounds__(512, 1)
attn_main(const float* __restrict__ values,
          const float* __restrict__ wscore)
{
    extern __shared__ __align__(16) char dsm[];
    const int tid  = threadIdx.x;
    const int lane = tid & 31, warp = tid >> 5;
    const int wm = warp >> 2, wn = warp & 3;    // 4 x 4
    const int tile = blockIdx.x, b = blockIdx.y;
    const int t0 = tile * TILE_T;

    __shared__ float s_sm[AD], w_sm[AD];
    __shared__ float e_sm[TILE_T], p_sm[TILE_T];
    __shared__ float redm[4], redl[4];
    __shared__ float m_sh;

    if (tid < AD) { s_sm[tid] = g_s[b * AD + tid]; w_sm[tid] = wscore[tid]; }
    if (tid < TILE_T) e_sm[tid] = 0.f;

    const float* vbase = values + ((size_t)b * T_LEN + t0) * VD;
    const uint32_t sbase = (uint32_t)__cvta_generic_to_shared(dsm);

    float acc[2][8][4];
#pragma unroll
    for (int i = 0; i < 2; i++)
#pragma unroll
        for (int j = 0; j < 8; j++)
#pragma unroll
            for (int k = 0; k < 4; k++) acc[i][j][k] = 0.f;

    // producers: A 2048 float4 segs (4/thread), B 2048 16B segs (4/thread)
    float4 av[4];
    auto ldgA = [&](int kc) {
#pragma unroll
        for (int r = 0; r < 4; r++) {
            int idx = tid + r * 512;
            int row = idx >> 4, seg = idx & 15;
            av[r] = __ldg((const float4*)(vbase + (size_t)row * VD + kc * KC) + seg);
        }
    };
    auto cpB = [&](int buf, int kc) {
#pragma unroll
        for (int r = 0; r < 4; r++) {
            int idx = tid + r * 512;
            int row = idx >> 3, seg = idx & 7;
            cp16(sbase + OFF_B + buf * B_TILE + row * ROW_B + seg * 16,
                 (const char*)g_wh + (size_t)row * (VD * 2) + kc * (KC * 2) + seg * 16);
        }
    };
    auto stsA = [&](int slot) {
#pragma unroll
        for (int r = 0; r < 4; r++) {
            int idx = tid + r * 512;
            int row = idx >> 4, seg = idx & 15;
            __half2 h0 = __floats2half2_rn(av[r].x, av[r].y);
            __half2 h1 = __floats2half2_rn(av[r].z, av[r].w);
            uint2 u = make_uint2(*(uint32_t*)&h0, *(uint32_t*)&h1);
            *(uint2*)(dsm + slot * A_SLOT + row * ROW_B + seg * 8) = u;
        }
    };

    // ldmatrix lane address components (proven mapping)
    const int aRowLane = (lane & 7) | (((lane >> 3) & 1) << 3);   // 0..15
    const int aColOff  = ((lane >> 4) & 1) * 16;
    const int aBaseRow = wm * 32 + aRowLane;
    const int bNLane   = ((lane >> 4) & 1) * 8 + (lane & 7);
    const int bColOff  = ((lane >> 3) & 1) * 16;
    const int bBaseRow = wn * 64 + bNLane;

    // prologue: chunk 0
    ldgA(0);
    cpB(0, 0);
    cp_commit();
    stsA(0);
    cp_wait<0>();
    __syncthreads();

    for (int kc = 0; kc < NKC; kc++) {
        if (kc + 1 < NKC) {
            ldgA(kc + 1);
            cpB((kc + 1) & 1, kc + 1);
            cp_commit();
        }
        // ---- mma: A slot kc, B buffer kc&1 ----
        {
            uint32_t abuf = sbase + kc * A_SLOT;
            uint32_t bbuf = sbase + OFF_B + (kc & 1) * B_TILE;
#pragma unroll
            for (int ks = 0; ks < 4; ks++) {
                uint32_t af[2][4];
#pragma unroll
                for (int i = 0; i < 2; i++)
                    ldsm_x4(af[i][0], af[i][1], af[i][2], af[i][3],
                            abuf + (aBaseRow + i * 16) * ROW_B + ks * 32 + aColOff);
#pragma unroll
                for (int jp = 0; jp < 4; jp++) {
                    uint32_t b0a, b1a, b0b, b1b;
                    ldsm_x4(b0a, b1a, b0b, b1b,
                            bbuf + (bBaseRow + jp * 16) * ROW_B + ks * 32 + bColOff);
#pragma unroll
                    for (int i = 0; i < 2; i++) {
                        mma_f16(acc[i][2*jp][0], acc[i][2*jp][1], acc[i][2*jp][2], acc[i][2*jp][3],
                                af[i][0], af[i][1], af[i][2], af[i][3], b0a, b1a);
                        mma_f16(acc[i][2*jp+1][0], acc[i][2*jp+1][1], acc[i][2*jp+1][2], acc[i][2*jp+1][3],
                                af[i][0], af[i][1], af[i][2], af[i][3], b0b, b1b);
                    }
                }
            }
        }
        if (kc + 1 < NKC) {
            stsA(kc + 1);
            cp_wait<0>();
            __syncthreads();
        }
    }

    // ---- score epilogue: e[t] = sum_a w[a]*tanh(keys[t,a] + s[a]) ----
    // tanh via f16x2 MUFU (1 inst / 2 elements); score sums stay f32.
#pragma unroll
    for (int i = 0; i < 2; i++) {
        float sA = 0.f, sB = 0.f;
#pragma unroll
        for (int j = 0; j < 8; j++) {
            int c0 = wn * 64 + j * 8 + 2 * (lane & 3);
            int c1 = c0 + 1;
            float2 tA = tanh2(acc[i][j][0] + s_sm[c0], acc[i][j][1] + s_sm[c1]);
            float2 tB = tanh2(acc[i][j][2] + s_sm[c0], acc[i][j][3] + s_sm[c1]);
            sA += w_sm[c0] * tA.x + w_sm[c1] * tA.y;
            sB += w_sm[c0] * tB.x + w_sm[c1] * tB.y;
        }
        sA += __shfl_xor_sync(0xffffffff, sA, 1);
        sA += __shfl_xor_sync(0xffffffff, sA, 2);
        sB += __shfl_xor_sync(0xffffffff, sB, 1);
        sB += __shfl_xor_sync(0xffffffff, sB, 2);
        if ((lane & 3) == 0) {
            int r0 = wm * 32 + i * 16 + (lane >> 2);
            atomicAdd(&e_sm[r0], sA);
            atomicAdd(&e_sm[r0 + 8], sB);
        }
    }
    __syncthreads();

    // ---- tile-local softmax stats (warps 0-3 cover 128 rows) ----
    if (tid < TILE_T) {
        float v = e_sm[tid];
#pragma unroll
        for (int o = 16; o > 0; o >>= 1) v = fmaxf(v, __shfl_xor_sync(0xffffffff, v, o));
        if (lane == 0) redm[warp] = v;
    }
    __syncthreads();
    if (tid == 0)
        m_sh = fmaxf(fmaxf(redm[0], redm[1]), fmaxf(redm[2], redm[3]));
    __syncthreads();
    float mt = m_sh;
    if (tid < TILE_T) {
        float e = e_sm[tid];
        float p = __expf(e - mt);
        p_sm[tid] = p;
        g_e[b * T_LEN + t0 + tid] = e;
#pragma unroll
        for (int o = 16; o > 0; o >>= 1) p += __shfl_xor_sync(0xffffffff, p, o);
        if (lane == 0) redl[warp] = p;
    }
    __syncthreads();
    if (tid == 0) {
        g_m[b * NTILE + tile] = mt;
        g_l[b * NTILE + tile] = redl[0] + redl[1] + redl[2] + redl[3];
    }
    __syncthreads();

    // ---- partial context from persistent fp16 A in smem ----
    {
        int v = tid & 255, half = tid >> 8;
        const char* abase = dsm + (v >> 6) * A_SLOT + (v & 63) * 2;
        float ca = 0.f;
#pragma unroll 8
        for (int t = 0; t < 64; t++) {
            const __half h = *(const __half*)(abase + (half * 64 + t) * ROW_B);
            ca += p_sm[half * 64 + t] * __half2float(h);
        }
        float* cacc = (float*)(dsm + OFF_B);   // B region free now
        cacc[half * 256 + v] = ca;
        __syncthreads();
        if (tid < VD)
            g_cp[((b * NTILE + tile) << 8) + tid] = cacc[tid] + cacc[256 + tid];
    }
}

// ============================================================================
// K2: combine — inline redundant stats (32-lane butterfly), then stream.
// grid (16 chunks, B) x 256 thr; chunk 0 also emits c.
// out layout: c [B,VD] then a [B,T]   (bv_score dropped: softmax-invariant)
// ============================================================================
__global__ void combine_kernel(float* __restrict__ out)
{
    int chunk = blockIdx.x, b = blockIdx.y, tid = threadIdx.x, lane = tid & 31;

    float m = g_m[b * NTILE + lane];
    float l = g_l[b * NTILE + lane];
    float M = m;
#pragma unroll
    for (int o = 16; o > 0; o >>= 1) M = fmaxf(M, __shfl_xor_sync(0xffffffff, M, o));
    float lw = l * __expf(m - M);
#pragma unroll
    for (int o = 16; o > 0; o >>= 1) lw += __shfl_xor_sync(0xffffffff, lw, o);
    float invL = 1.0f / lw;

    float* a_out = out + BATCH * VD;
    int t = chunk * 256 + tid;
    a_out[b * T_LEN + t] = __expf(g_e[b * T_LEN + t] - M) * invL;
    if (chunk == 0) {
        float acc = 0.f;
#pragma unroll
        for (int i = 0; i < NTILE; i++)
            acc += g_cp[((b * NTILE + i) << 8) + tid] * __expf(g_m[b * NTILE + i] - M);
        out[b * VD + tid] = acc * invL;
    }
}

// ============================================================================
// launch
// ============================================================================
extern "C" void kernel_launch(void* const* d_in, const int* in_sizes, int n_in,
                              void* d_out, int out_size)
{
    const float* query  = (const float*)d_in[0];
    const float* values = (const float*)d_in[1];
    const float* Wq     = (const float*)d_in[2];
    const float* bq     = (const float*)d_in[3];
    const float* Wv     = (const float*)d_in[4];
    const float* bv     = (const float*)d_in[5];
    const float* wsc    = (const float*)d_in[6];
    // d_in[7] = bv_score: additive constant inside softmax -> no effect
    (void)in_sizes; (void)n_in; (void)out_size;
    float* out = (float*)d_out;

    cudaFuncSetAttribute(attn_main, cudaFuncAttributeMaxDynamicSharedMemorySize, DSMEM_BYTES);

    qproj_kernel<<<dim3(32, 16), 256>>>(query, Wq, bq, bv, Wv);
    attn_main<<<dim3(NTILE, BATCH), 512, DSMEM_BYTES>>>(values, wsc);
    combine_kernel<<<dim3(16, BATCH), 256>>>(out);
}

// round 17
// speedup vs baseline: 1.1075x; 1.1075x over previous
#include <cuda_runtime.h>
#include <cuda_fp16.h>
#include <cstdint>

#define T_LEN  4096
#define BATCH  32
#define AD     256
#define VD     256
#define TILE_T 128
#define NTILE  (T_LEN / TILE_T)   // 32
#define KC     64                 // K floats per pipeline chunk
#define NKC    (VD / KC)          // 4

// ---- smem layout (bytes): fp16 tiles, 144B padded rows (64 halves + 16B pad)
#define ROW_B   144
#define A_SLOT  (TILE_T * ROW_B)          // 18432 ; 4 persistent slots
#define OFF_B   (4 * A_SLOT)              // 73728
#define B_TILE  (AD * ROW_B)              // 36864 ; x2 double buffered
#define DSMEM_BYTES (OFF_B + 2 * B_TILE)  // 147456

// ---- device scratch ----
__device__ float   g_s[BATCH * AD];
__device__ float   g_e[BATCH * T_LEN];
__device__ float   g_m[BATCH * NTILE];
__device__ float   g_l[BATCH * NTILE];
__device__ float   g_cp[BATCH * NTILE * VD];
__device__ __half2 g_wh[AD * VD / 2];     // Wv fp16, row-major [a][k]

// ---- helpers ----
__device__ __forceinline__ void cp16(uint32_t dst, const void* src) {
    asm volatile("cp.async.cg.shared.global [%0], [%1], 16;" :: "r"(dst), "l"(src));
}
__device__ __forceinline__ void cp_commit() { asm volatile("cp.async.commit_group;"); }
template <int N> __device__ __forceinline__ void cp_wait() {
    asm volatile("cp.async.wait_group %0;" :: "n"(N));
}
__device__ __forceinline__ void ldsm_x4(uint32_t& r0, uint32_t& r1, uint32_t& r2,
                                        uint32_t& r3, uint32_t addr) {
    asm volatile("ldmatrix.sync.aligned.m8n8.x4.shared.b16 {%0,%1,%2,%3}, [%4];"
                 : "=r"(r0), "=r"(r1), "=r"(r2), "=r"(r3) : "r"(addr));
}
__device__ __forceinline__ void mma_f16(
    float& d0, float& d1, float& d2, float& d3,
    uint32_t a0, uint32_t a1, uint32_t a2, uint32_t a3,
    uint32_t b0, uint32_t b1)
{
    asm volatile(
        "mma.sync.aligned.m16n8k16.row.col.f32.f16.f16.f32 "
        "{%0,%1,%2,%3}, {%4,%5,%6,%7}, {%8,%9}, {%0,%1,%2,%3};"
        : "+f"(d0), "+f"(d1), "+f"(d2), "+f"(d3)
        : "r"(a0), "r"(a1), "r"(a2), "r"(a3), "r"(b0), "r"(b1));
}
// f32 tanh: 1 MUFU instruction per element, no converts (measured-best form)
__device__ __forceinline__ float tanha(float x) {
    float y;
    asm("tanh.approx.f32 %0, %1;" : "=f"(y) : "f"(x));
    return y;
}

// ============================================================================
// K0: qproj — grid (32 a-chunks, 16 b-groups) = 512 blocks x 256 thr.
// Warp per a-row, 2 b's per block. Also converts a Wv slice to fp16.
// ============================================================================
__global__ void qproj_kernel(const float* __restrict__ query,
                             const float* __restrict__ Wq,
                             const float* __restrict__ bq,
                             const float* __restrict__ bv,
                             const float* __restrict__ Wv)
{
    int tid = threadIdx.x, warp = tid >> 5, lane = tid & 31;
    int bg = blockIdx.y;                       // b-group: 2 b's
    __shared__ float q_sm[2 * AD];             // 512 floats

    // Wv conversion: 32768 half2 over 512 blocks -> 64 per block
    if (tid < 64) {
        int i = (blockIdx.y * 32 + blockIdx.x) * 64 + tid;
        float2 v = ((const float2*)Wv)[i];
        g_wh[i] = __floats2half2_rn(v.x, v.y);
    }

    // 512 floats, 256 threads -> two writes per thread
    q_sm[tid]       = query[bg * 2 * AD + tid];
    q_sm[tid + 256] = query[bg * 2 * AD + tid + 256];
    __syncthreads();

    int a = blockIdx.x * 8 + warp;
    const float* wrow = Wq + (size_t)a * AD;
    float wr[8];
#pragma unroll
    for (int i = 0; i < 8; i++) wr[i] = wrow[lane + 32 * i];
    float bias = bq[a] + bv[a];

#pragma unroll
    for (int i = 0; i < 2; i++) {
        float acc = 0.f;
#pragma unroll
        for (int k = 0; k < 8; k++) acc += wr[k] * q_sm[i * AD + lane + 32 * k];
#pragma unroll
        for (int o = 16; o > 0; o >>= 1) acc += __shfl_xor_sync(0xffffffff, acc, o);
        if (lane == 0) g_s[(bg * 2 + i) * AD + a] = acc + bias;
    }
}

// ============================================================================
// K1: per (b, 128-row T-tile). 512 threads = 16 warps in 4(m)x4(n) grid,
// each warp owns 32x64 of C. KC=64 (4 chunks). A persists in smem (fp16,
// 4 slots) so the context pass reads smem. Epilogue tanh: f32 MUFU.
// ============================================================================
__global__ void __launch_bounds__(512, 1)
attn_main(const float* __restrict__ values,
          const float* __restrict__ wscore)
{
    extern __shared__ __align__(16) char dsm[];
    const int tid  = threadIdx.x;
    const int lane = tid & 31, warp = tid >> 5;
    const int wm = warp >> 2, wn = warp & 3;    // 4 x 4
    const int tile = blockIdx.x, b = blockIdx.y;
    const int t0 = tile * TILE_T;

    __shared__ float s_sm[AD], w_sm[AD];
    __shared__ float e_sm[TILE_T], p_sm[TILE_T];
    __shared__ float redm[4], redl[4];
    __shared__ float m_sh;

    if (tid < AD) { s_sm[tid] = g_s[b * AD + tid]; w_sm[tid] = wscore[tid]; }
    if (tid < TILE_T) e_sm[tid] = 0.f;

    const float* vbase = values + ((size_t)b * T_LEN + t0) * VD;
    const uint32_t sbase = (uint32_t)__cvta_generic_to_shared(dsm);

    float acc[2][8][4];
#pragma unroll
    for (int i = 0; i < 2; i++)
#pragma unroll
        for (int j = 0; j < 8; j++)
#pragma unroll
            for (int k = 0; k < 4; k++) acc[i][j][k] = 0.f;

    // producers: A 2048 float4 segs (4/thread), B 2048 16B segs (4/thread)
    float4 av[4];
    auto ldgA = [&](int kc) {
#pragma unroll
        for (int r = 0; r < 4; r++) {
            int idx = tid + r * 512;
            int row = idx >> 4, seg = idx & 15;
            av[r] = __ldg((const float4*)(vbase + (size_t)row * VD + kc * KC) + seg);
        }
    };
    auto cpB = [&](int buf, int kc) {
#pragma unroll
        for (int r = 0; r < 4; r++) {
            int idx = tid + r * 512;
            int row = idx >> 3, seg = idx & 7;
            cp16(sbase + OFF_B + buf * B_TILE + row * ROW_B + seg * 16,
                 (const char*)g_wh + (size_t)row * (VD * 2) + kc * (KC * 2) + seg * 16);
        }
    };
    auto stsA = [&](int slot) {
#pragma unroll
        for (int r = 0; r < 4; r++) {
            int idx = tid + r * 512;
            int row = idx >> 4, seg = idx & 15;
            __half2 h0 = __floats2half2_rn(av[r].x, av[r].y);
            __half2 h1 = __floats2half2_rn(av[r].z, av[r].w);
            uint2 u = make_uint2(*(uint32_t*)&h0, *(uint32_t*)&h1);
            *(uint2*)(dsm + slot * A_SLOT + row * ROW_B + seg * 8) = u;
        }
    };

    // ldmatrix lane address components (proven mapping)
    const int aRowLane = (lane & 7) | (((lane >> 3) & 1) << 3);   // 0..15
    const int aColOff  = ((lane >> 4) & 1) * 16;
    const int aBaseRow = wm * 32 + aRowLane;
    const int bNLane   = ((lane >> 4) & 1) * 8 + (lane & 7);
    const int bColOff  = ((lane >> 3) & 1) * 16;
    const int bBaseRow = wn * 64 + bNLane;

    // prologue: chunk 0
    ldgA(0);
    cpB(0, 0);
    cp_commit();
    stsA(0);
    cp_wait<0>();
    __syncthreads();

    for (int kc = 0; kc < NKC; kc++) {
        if (kc + 1 < NKC) {
            ldgA(kc + 1);
            cpB((kc + 1) & 1, kc + 1);
            cp_commit();
        }
        // ---- mma: A slot kc, B buffer kc&1 ----
        {
            uint32_t abuf = sbase + kc * A_SLOT;
            uint32_t bbuf = sbase + OFF_B + (kc & 1) * B_TILE;
#pragma unroll
            for (int ks = 0; ks < 4; ks++) {
                uint32_t af[2][4];
#pragma unroll
                for (int i = 0; i < 2; i++)
                    ldsm_x4(af[i][0], af[i][1], af[i][2], af[i][3],
                            abuf + (aBaseRow + i * 16) * ROW_B + ks * 32 + aColOff);
#pragma unroll
                for (int jp = 0; jp < 4; jp++) {
                    uint32_t b0a, b1a, b0b, b1b;
                    ldsm_x4(b0a, b1a, b0b, b1b,
                            bbuf + (bBaseRow + jp * 16) * ROW_B + ks * 32 + bColOff);
#pragma unroll
                    for (int i = 0; i < 2; i++) {
                        mma_f16(acc[i][2*jp][0], acc[i][2*jp][1], acc[i][2*jp][2], acc[i][2*jp][3],
                                af[i][0], af[i][1], af[i][2], af[i][3], b0a, b1a);
                        mma_f16(acc[i][2*jp+1][0], acc[i][2*jp+1][1], acc[i][2*jp+1][2], acc[i][2*jp+1][3],
                                af[i][0], af[i][1], af[i][2], af[i][3], b0b, b1b);
                    }
                }
            }
        }
        if (kc + 1 < NKC) {
            stsA(kc + 1);
            cp_wait<0>();
            __syncthreads();
        }
    }

    // ---- score epilogue: e[t] = sum_a w[a]*tanh(keys[t,a] + s[a]) ----
#pragma unroll
    for (int i = 0; i < 2; i++) {
        float sA = 0.f, sB = 0.f;
#pragma unroll
        for (int j = 0; j < 8; j++) {
            int c0 = wn * 64 + j * 8 + 2 * (lane & 3);
            int c1 = c0 + 1;
            sA += w_sm[c0] * tanha(acc[i][j][0] + s_sm[c0])
                + w_sm[c1] * tanha(acc[i][j][1] + s_sm[c1]);
            sB += w_sm[c0] * tanha(acc[i][j][2] + s_sm[c0])
                + w_sm[c1] * tanha(acc[i][j][3] + s_sm[c1]);
        }
        sA += __shfl_xor_sync(0xffffffff, sA, 1);
        sA += __shfl_xor_sync(0xffffffff, sA, 2);
        sB += __shfl_xor_sync(0xffffffff, sB, 1);
        sB += __shfl_xor_sync(0xffffffff, sB, 2);
        if ((lane & 3) == 0) {
            int r0 = wm * 32 + i * 16 + (lane >> 2);
            atomicAdd(&e_sm[r0], sA);
            atomicAdd(&e_sm[r0 + 8], sB);
        }
    }
    __syncthreads();

    // ---- tile-local softmax stats (warps 0-3 cover 128 rows) ----
    if (tid < TILE_T) {
        float v = e_sm[tid];
#pragma unroll
        for (int o = 16; o > 0; o >>= 1) v = fmaxf(v, __shfl_xor_sync(0xffffffff, v, o));
        if (lane == 0) redm[warp] = v;
    }
    __syncthreads();
    if (tid == 0)
        m_sh = fmaxf(fmaxf(redm[0], redm[1]), fmaxf(redm[2], redm[3]));
    __syncthreads();
    float mt = m_sh;
    if (tid < TILE_T) {
        float e = e_sm[tid];
        float p = __expf(e - mt);
        p_sm[tid] = p;
        g_e[b * T_LEN + t0 + tid] = e;
#pragma unroll
        for (int o = 16; o > 0; o >>= 1) p += __shfl_xor_sync(0xffffffff, p, o);
        if (lane == 0) redl[warp] = p;
    }
    __syncthreads();
    if (tid == 0) {
        g_m[b * NTILE + tile] = mt;
        g_l[b * NTILE + tile] = redl[0] + redl[1] + redl[2] + redl[3];
    }
    __syncthreads();

    // ---- partial context from persistent fp16 A in smem ----
    {
        int v = tid & 255, half = tid >> 8;
        const char* abase = dsm + (v >> 6) * A_SLOT + (v & 63) * 2;
        float ca = 0.f;
#pragma unroll 8
        for (int t = 0; t < 64; t++) {
            const __half h = *(const __half*)(abase + (half * 64 + t) * ROW_B);
            ca += p_sm[half * 64 + t] * __half2float(h);
        }
        float* cacc = (float*)(dsm + OFF_B);   // B region free now
        cacc[half * 256 + v] = ca;
        __syncthreads();
        if (tid < VD)
            g_cp[((b * NTILE + tile) << 8) + tid] = cacc[tid] + cacc[256 + tid];
    }
}

// ============================================================================
// K2: combine — inline redundant stats (32-lane butterfly), then stream.
// grid (16 chunks, B) x 256 thr; chunk 0 also emits c.
// out layout: c [B,VD] then a [B,T]   (bv_score dropped: softmax-invariant)
// ============================================================================
__global__ void combine_kernel(float* __restrict__ out)
{
    int chunk = blockIdx.x, b = blockIdx.y, tid = threadIdx.x, lane = tid & 31;

    float m = g_m[b * NTILE + lane];
    float l = g_l[b * NTILE + lane];
    float M = m;
#pragma unroll
    for (int o = 16; o > 0; o >>= 1) M = fmaxf(M, __shfl_xor_sync(0xffffffff, M, o));
    float lw = l * __expf(m - M);
#pragma unroll
    for (int o = 16; o > 0; o >>= 1) lw += __shfl_xor_sync(0xffffffff, lw, o);
    float invL = 1.0f / lw;

    float* a_out = out + BATCH * VD;
    int t = chunk * 256 + tid;
    a_out[b * T_LEN + t] = __expf(g_e[b * T_LEN + t] - M) * invL;
    if (chunk == 0) {
        float acc = 0.f;
#pragma unroll
        for (int i = 0; i < NTILE; i++)
            acc += g_cp[((b * NTILE + i) << 8) + tid] * __expf(g_m[b * NTILE + i] - M);
        out[b * VD + tid] = acc * invL;
    }
}

// ============================================================================
// launch
// ============================================================================
extern "C" void kernel_launch(void* const* d_in, const int* in_sizes, int n_in,
                              void* d_out, int out_size)
{
    const float* query  = (const float*)d_in[0];
    const float* values = (const float*)d_in[1];
    const float* Wq     = (const float*)d_in[2];
    const float* bq     = (const float*)d_in[3];
    const float* Wv     = (const float*)d_in[4];
    const float* bv     = (const float*)d_in[5];
    const float* wsc    = (const float*)d_in[6];
    // d_in[7] = bv_score: additive constant inside softmax -> no effect
    (void)in_sizes; (void)n_in; (void)out_size;
    float* out = (float*)d_out;

    cudaFuncSetAttribute(attn_main, cudaFuncAttributeMaxDynamicSharedMemorySize, DSMEM_BYTES);

    qproj_kernel<<<dim3(32, 16), 256>>>(query, Wq, bq, bv, Wv);
    attn_main<<<dim3(NTILE, BATCH), 512, DSMEM_BYTES>>>(values, wsc);
    combine_kernel<<<dim3(16, BATCH), 256>>>(out);
}